// round 1
// baseline (speedup 1.0000x reference)
#include <cuda_runtime.h>
#include <cuda_bf16.h>
#include <cstdint>

// Problem constants
constexpr int B = 128, T = 16, L = 196, E = 512, H = 1024, V = 32000;

// ---------------- scratch (device globals; no allocations allowed) ----------
__device__ float g_keys[(size_t)B * L * H];     // 103 MB
__device__ float g_h[B * H];
__device__ float g_c[B * H];
__device__ float g_q[B * H];
__device__ float g_e[B * L];
__device__ float g_alpha[B * L];
__device__ float g_z[B * E];
__device__ float g_gbuf[B * E];
__device__ float g_ctx[B * 2 * E];
__device__ float g_gates[B * 4 * H];
__device__ float g_logits[(size_t)B * V];       // 16.4 MB
__device__ float g_capemb[(size_t)B * T * E];
__device__ float g_mean[B * E];

// ---------------- helpers ---------------------------------------------------
__device__ __forceinline__ float warpReduceSum(float v) {
    #pragma unroll
    for (int o = 16; o > 0; o >>= 1) v += __shfl_xor_sync(0xFFFFFFFFu, v, o);
    return v;
}
__device__ __forceinline__ float sigmoidf(float x) {
    return 1.0f / (1.0f + __expf(-x));
}

// ---------------- generic fp32 SGEMM: C = A[MxK] @ W[KxN] (+bias) (+=) ------
// Requires M%64==0, N%64==0, K%16==0 (all shapes here satisfy this).
constexpr int BM = 64, BN = 64, BK = 16, TM = 4, TN = 4;

template <bool ACC, bool BIAS>
__global__ void sgemm(const float* __restrict__ A, const float* __restrict__ W,
                      const float* __restrict__ bias, float* __restrict__ C,
                      int M, int N, int K) {
    __shared__ float As[BK][BM + 1];
    __shared__ float Ws[BK][BN];

    const int tid  = threadIdx.y * 16 + threadIdx.x;
    const int row0 = blockIdx.y * BM;
    const int col0 = blockIdx.x * BN;

    const int aRow  = tid >> 2;          // 0..63
    const int aCol4 = (tid & 3) * 4;     // 0,4,8,12
    const int wRow  = tid >> 4;          // 0..15
    const int wCol4 = (tid & 15) * 4;

    float acc[TM][TN] = {};

    for (int k0 = 0; k0 < K; k0 += BK) {
        float4 av = *(const float4*)(A + (size_t)(row0 + aRow) * K + k0 + aCol4);
        As[aCol4 + 0][aRow] = av.x;
        As[aCol4 + 1][aRow] = av.y;
        As[aCol4 + 2][aRow] = av.z;
        As[aCol4 + 3][aRow] = av.w;
        *(float4*)&Ws[wRow][wCol4] =
            *(const float4*)(W + (size_t)(k0 + wRow) * N + col0 + wCol4);
        __syncthreads();

        #pragma unroll
        for (int k = 0; k < BK; k++) {
            float a[TM], b[TN];
            #pragma unroll
            for (int i = 0; i < TM; i++) a[i] = As[k][threadIdx.y * TM + i];
            #pragma unroll
            for (int j = 0; j < TN; j++) b[j] = Ws[k][threadIdx.x * TN + j];
            #pragma unroll
            for (int i = 0; i < TM; i++)
                #pragma unroll
                for (int j = 0; j < TN; j++)
                    acc[i][j] = fmaf(a[i], b[j], acc[i][j]);
        }
        __syncthreads();
    }

    #pragma unroll
    for (int i = 0; i < TM; i++) {
        const int r = row0 + threadIdx.y * TM + i;
        #pragma unroll
        for (int j = 0; j < TN; j++) {
            const int cix = col0 + threadIdx.x * TN + j;
            float v = acc[i][j];
            if (BIAS) v += bias[cix];
            if (ACC) C[(size_t)r * N + cix] += v;
            else     C[(size_t)r * N + cix] = v;
        }
    }
}

// ---------------- small kernels ---------------------------------------------
__global__ void gather_emb(const int* __restrict__ cap, const float* __restrict__ emb,
                           float* __restrict__ capemb) {
    int idx = blockIdx.x * blockDim.x + threadIdx.x;      // B*T*E
    int e  = idx % E;
    int bt = idx / E;                                     // b*T + t
    int tok = cap[bt];
    capemb[idx] = emb[(size_t)tok * E + e];
}

__global__ void row_mean(const float* __restrict__ feats, float* __restrict__ mean) {
    int b = blockIdx.x;
    int e = threadIdx.x;                                  // blockDim = E = 512
    float s = 0.f;
    const float* base = feats + (size_t)b * L * E + e;
    for (int l = 0; l < L; l++) s += base[(size_t)l * E];
    mean[b * E + e] = s * (1.0f / (float)L);
}

__global__ void attn_e(const float* __restrict__ q, const float* __restrict__ Va,
                       const float* __restrict__ bva, float* __restrict__ e) {
    int l = blockIdx.x, b = blockIdx.y;
    const float* kk = g_keys + ((size_t)b * L + l) * H;
    const float* qq = q + (size_t)b * H;
    float s = 0.f;
    for (int i = threadIdx.x; i < H; i += 128) {
        float v = fmaxf(qq[i] + kk[i], 0.f);
        s = fmaf(v, Va[i], s);
    }
    s = warpReduceSum(s);
    __shared__ float sm[4];
    if ((threadIdx.x & 31) == 0) sm[threadIdx.x >> 5] = s;
    __syncthreads();
    if (threadIdx.x == 0)
        e[b * L + l] = sm[0] + sm[1] + sm[2] + sm[3] + bva[0];
}

__global__ void softmax_L(const float* __restrict__ e, float* __restrict__ alpha) {
    int b = blockIdx.x;
    int tid = threadIdx.x;                                // blockDim = 256
    __shared__ float sm[256];
    float v = (tid < L) ? e[b * L + tid] : -1e30f;
    sm[tid] = v; __syncthreads();
    for (int s = 128; s > 0; s >>= 1) { if (tid < s) sm[tid] = fmaxf(sm[tid], sm[tid + s]); __syncthreads(); }
    float m = sm[0]; __syncthreads();
    float ex = (tid < L) ? __expf(v - m) : 0.f;
    sm[tid] = ex; __syncthreads();
    for (int s = 128; s > 0; s >>= 1) { if (tid < s) sm[tid] += sm[tid + s]; __syncthreads(); }
    float inv = 1.0f / sm[0];
    if (tid < L) alpha[b * L + tid] = ex * inv;
}

__global__ void z_sum(const float* __restrict__ alpha, const float* __restrict__ feats,
                      float* __restrict__ z) {
    int b = blockIdx.x;
    __shared__ float al[L];
    for (int l = threadIdx.x; l < L; l += blockDim.x) al[l] = alpha[b * L + l];
    __syncthreads();
    int e = threadIdx.x;                                  // blockDim = E = 512
    float s = 0.f;
    const float* base = feats + (size_t)b * L * E + e;
    for (int l = 0; l < L; l++) s = fmaf(al[l], base[(size_t)l * E], s);
    z[b * E + e] = s;
}

__global__ void build_ctx(const float* __restrict__ z, const float* __restrict__ gbuf,
                          const float* __restrict__ capemb, int t, float* __restrict__ ctx) {
    int idx = blockIdx.x * blockDim.x + threadIdx.x;      // B*E
    int b = idx / E, e = idx % E;
    float zg = z[idx] * sigmoidf(gbuf[idx]);
    ctx[(size_t)b * 2 * E + e]     = zg;
    ctx[(size_t)b * 2 * E + E + e] = capemb[((size_t)b * T + t) * E + e];
}

__global__ void lstm_elem(const float* __restrict__ gates, float* __restrict__ h,
                          float* __restrict__ c) {
    int idx = blockIdx.x * blockDim.x + threadIdx.x;      // B*H
    int b = idx / H, j = idx % H;
    const float* g = gates + (size_t)b * 4 * H;
    float i_ = sigmoidf(g[j]);
    float f_ = sigmoidf(g[H + j]);
    float gg = tanhf(g[2 * H + j]);
    float o_ = sigmoidf(g[3 * H + j]);
    float cn = f_ * c[idx] + i_ * gg;
    c[idx] = cn;
    h[idx] = o_ * tanhf(cn);
}

__global__ void softmax_V(const float* __restrict__ logits, float* __restrict__ out, int t) {
    int b = blockIdx.x;
    int tid = threadIdx.x;                                // blockDim = 256
    const float* x = logits + (size_t)b * V;
    float* y = out + ((size_t)b * T + t) * V;
    __shared__ float sm[8];

    float m = -1e30f;
    for (int i = tid; i < V; i += 256) m = fmaxf(m, x[i]);
    #pragma unroll
    for (int o = 16; o > 0; o >>= 1) m = fmaxf(m, __shfl_xor_sync(0xFFFFFFFFu, m, o));
    if ((tid & 31) == 0) sm[tid >> 5] = m;
    __syncthreads();
    float mm = fmaxf(fmaxf(fmaxf(sm[0], sm[1]), fmaxf(sm[2], sm[3])),
                     fmaxf(fmaxf(sm[4], sm[5]), fmaxf(sm[6], sm[7])));
    __syncthreads();

    float s = 0.f;
    for (int i = tid; i < V; i += 256) s += __expf(x[i] - mm);
    s = warpReduceSum(s);
    if ((tid & 31) == 0) sm[tid >> 5] = s;
    __syncthreads();
    float ss = sm[0] + sm[1] + sm[2] + sm[3] + sm[4] + sm[5] + sm[6] + sm[7];
    float inv = 1.0f / ss;
    for (int i = tid; i < V; i += 256) y[i] = __expf(x[i] - mm) * inv;
}

// ---------------- launch ------------------------------------------------------
extern "C" void kernel_launch(void* const* d_in, const int* in_sizes, int n_in,
                              void* d_out, int out_size) {
    const int*   cap      = (const int*)  d_in[0];
    const float* feats    = (const float*)d_in[1];
    const float* emb      = (const float*)d_in[2];
    const float* W_init_h = (const float*)d_in[3];
    const float* b_init_h = (const float*)d_in[4];
    const float* W_init_c = (const float*)d_in[5];
    const float* b_init_c = (const float*)d_in[6];
    const float* W_a      = (const float*)d_in[7];
    const float* b_a      = (const float*)d_in[8];
    const float* U_a      = (const float*)d_in[9];
    const float* b_ua     = (const float*)d_in[10];
    const float* V_a      = (const float*)d_in[11];
    const float* b_va     = (const float*)d_in[12];
    const float* W_beta   = (const float*)d_in[13];
    const float* b_beta   = (const float*)d_in[14];
    const float* W_lstm   = (const float*)d_in[15];
    const float* U_lstm   = (const float*)d_in[16];
    const float* b_lstm   = (const float*)d_in[17];
    const float* W_out    = (const float*)d_in[18];
    const float* b_out    = (const float*)d_in[19];
    float* out = (float*)d_out;

    float *keys, *h, *c, *q, *eb, *alpha, *z, *gbuf, *ctx, *gates, *logits, *capemb, *meanv;
    cudaGetSymbolAddress((void**)&keys,   g_keys);
    cudaGetSymbolAddress((void**)&h,      g_h);
    cudaGetSymbolAddress((void**)&c,      g_c);
    cudaGetSymbolAddress((void**)&q,      g_q);
    cudaGetSymbolAddress((void**)&eb,     g_e);
    cudaGetSymbolAddress((void**)&alpha,  g_alpha);
    cudaGetSymbolAddress((void**)&z,      g_z);
    cudaGetSymbolAddress((void**)&gbuf,   g_gbuf);
    cudaGetSymbolAddress((void**)&ctx,    g_ctx);
    cudaGetSymbolAddress((void**)&gates,  g_gates);
    cudaGetSymbolAddress((void**)&logits, g_logits);
    cudaGetSymbolAddress((void**)&capemb, g_capemb);
    cudaGetSymbolAddress((void**)&meanv,  g_mean);

    const dim3 tb(16, 16);

    // ---- prologue ----
    gather_emb<<<(B * T * E) / 256, 256>>>(cap, emb, capemb);
    row_mean<<<B, E>>>(feats, meanv);
    sgemm<false, true><<<dim3(H / BN, B / BM), tb>>>(meanv, W_init_h, b_init_h, h, B, H, E);
    sgemm<false, true><<<dim3(H / BN, B / BM), tb>>>(meanv, W_init_c, b_init_c, c, B, H, E);
    // keys = image_feats @ U_a + b_ua   ([B*L, E] @ [E, H])
    sgemm<false, true><<<dim3(H / BN, (B * L) / BM), tb>>>(feats, U_a, b_ua, keys, B * L, H, E);

    // ---- time steps ----
    for (int t = 0; t < T; t++) {
        // q = h @ W_a + b_a
        sgemm<false, true><<<dim3(H / BN, B / BM), tb>>>(h, W_a, b_a, q, B, H, H);
        // e = relu(q + keys) @ V_a + b_va
        attn_e<<<dim3(L, B), 128>>>(q, V_a, b_va, eb);
        softmax_L<<<B, 256>>>(eb, alpha);
        // z = sum_l alpha * feats
        z_sum<<<B, E>>>(alpha, feats, z);
        // beta gate: gbuf = h @ W_beta + b_beta
        sgemm<false, true><<<dim3(E / BN, B / BM), tb>>>(h, W_beta, b_beta, gbuf, B, E, H);
        // ctx = [z * sigmoid(gbuf), x_t]
        build_ctx<<<(B * E) / 256, 256>>>(z, gbuf, capemb, t, ctx);
        // gates = ctx @ W_lstm + b_lstm ; gates += h @ U_lstm
        sgemm<false, true><<<dim3(4 * H / BN, B / BM), tb>>>(ctx, W_lstm, b_lstm, gates, B, 4 * H, 2 * E);
        sgemm<true,  false><<<dim3(4 * H / BN, B / BM), tb>>>(h, U_lstm, nullptr, gates, B, 4 * H, H);
        lstm_elem<<<(B * H) / 256, 256>>>(gates, h, c);
        // logits = h @ W_out + b_out ; out[:, t, :] = softmax(logits)
        sgemm<false, true><<<dim3(V / BN, B / BM), tb>>>(h, W_out, b_out, logits, B, V, H);
        softmax_V<<<B, 256>>>(logits, out, t);
    }
}

// round 2
// speedup vs baseline: 3.7499x; 3.7499x over previous
#include <cuda_runtime.h>
#include <cuda_bf16.h>
#include <cstdint>

// Problem constants
constexpr int B = 128, T = 16, L = 196, E = 512, H = 1024, V = 32000;

// ---------------- scratch (device globals; no allocations allowed) ----------
__device__ __nv_bfloat16 g_keys_bf[(size_t)B * L * H];        // 51.4 MB
__device__ __nv_bfloat16 g_wout_bf[(size_t)H * V];            // 65.5 MB
__device__ __nv_bfloat16 g_wg_bf[(size_t)2048 * 4096];        // 16.8 MB
__device__ __nv_bfloat16 g_wqb_bf[(size_t)1024 * 1536];       // 3.1 MB
__device__ float g_bqb[1536];
__device__ float g_h[B * H];
__device__ float g_c[B * H];
__device__ float g_qb[B * 1536];
__device__ float g_e[B * L];
__device__ float g_alpha[B * L];
__device__ float g_ctx2[B * 2048];
__device__ float g_gates[B * 4 * H];
__device__ float g_logits[(size_t)B * V];                     // 16.4 MB
__device__ float g_capemb[(size_t)B * T * E];
__device__ float g_mean[B * E];

// ---------------- helpers ---------------------------------------------------
__device__ __forceinline__ float warpReduceSum(float v) {
    #pragma unroll
    for (int o = 16; o > 0; o >>= 1) v += __shfl_xor_sync(0xFFFFFFFFu, v, o);
    return v;
}
__device__ __forceinline__ float sigmoidf(float x) {
    return 1.0f / (1.0f + __expf(-x));
}

__device__ __forceinline__ void ldsm_x4(uint32_t* r, uint32_t addr) {
    asm volatile("ldmatrix.sync.aligned.m8n8.x4.shared.b16 {%0,%1,%2,%3}, [%4];"
                 : "=r"(r[0]), "=r"(r[1]), "=r"(r[2]), "=r"(r[3]) : "r"(addr));
}
__device__ __forceinline__ void ldsm_x4_t(uint32_t* r, uint32_t addr) {
    asm volatile("ldmatrix.sync.aligned.m8n8.x4.trans.shared.b16 {%0,%1,%2,%3}, [%4];"
                 : "=r"(r[0]), "=r"(r[1]), "=r"(r[2]), "=r"(r[3]) : "r"(addr));
}
__device__ __forceinline__ void mma_bf16(float* c, const uint32_t* a, uint32_t b0, uint32_t b1) {
    asm volatile(
        "mma.sync.aligned.m16n8k16.row.col.f32.bf16.bf16.f32 "
        "{%0,%1,%2,%3},{%4,%5,%6,%7},{%8,%9},{%0,%1,%2,%3};"
        : "+f"(c[0]), "+f"(c[1]), "+f"(c[2]), "+f"(c[3])
        : "r"(a[0]), "r"(a[1]), "r"(a[2]), "r"(a[3]), "r"(b0), "r"(b1));
}

// ---------------- tensor-core GEMM: C = A[MxK](f32) @ B[KxN] (+bias) --------
// BM=64 BN=64 BK=32, 128 threads (4 warps, 2x2 warp grid of 32x32 warp tiles).
// Requires M%64==0, N%64==0, K%32==0.
constexpr int BM = 64, BN = 64, BK = 32;
constexpr int LDA = 40;   // A smem row stride (bf16 elems), conflict-free for ldmatrix
constexpr int LDB = 72;   // B smem row stride
constexpr int ABYTES = BM * LDA * 2;  // 5120
constexpr int BBYTES = BK * LDB * 2;  // 4608

template <bool BSRC_BF, bool OUT_BF, bool BIAS>
__global__ __launch_bounds__(128) void gemm_tc(
    const float* __restrict__ A, const void* __restrict__ Bv,
    const float* __restrict__ bias, void* __restrict__ Cv,
    int M, int N, int K)
{
    __shared__ __align__(16) __nv_bfloat16 As[2][BM * LDA];
    __shared__ __align__(16) __nv_bfloat16 Bs[2][BK * LDB];

    const int tid  = threadIdx.x;
    const int lane = tid & 31;
    const int warp = tid >> 5;
    const int wm = (warp & 1) * 32;
    const int wn = (warp >> 1) * 32;
    const int bm = blockIdx.y * BM;
    const int bn = blockIdx.x * BN;

    // ---- global load mappings ----
    const int ar = tid >> 3;            // 0..15
    const int ac = (tid & 7) * 4;       // 0..28
    // B bf16 src: row tid>>3 (0..15), col (tid&7)*8  (2 passes of 16 rows)
    // B f32  src: row tid>>4 (0..7),  col (tid&15)*4 (4 passes of 8 rows)
    const int br16 = tid >> 3, bc16 = (tid & 7) * 8;
    const int br32 = tid >> 4, bc32 = (tid & 15) * 4;

    const __nv_bfloat16* Bb = (const __nv_bfloat16*)Bv;
    const float*         Bf = (const float*)Bv;

    float4 pa[4];
    uint4  pb16[2];
    float4 pb32[4];

    auto loadA = [&](int k0) {
        const float* Ap = A + (size_t)(bm + ar) * K + k0 + ac;
        #pragma unroll
        for (int p = 0; p < 4; p++) pa[p] = *(const float4*)(Ap + (size_t)p * 16 * K);
    };
    auto storeA = [&](int buf) {
        #pragma unroll
        for (int p = 0; p < 4; p++) {
            __nv_bfloat162* d = (__nv_bfloat162*)&As[buf][(ar + p * 16) * LDA + ac];
            d[0] = __floats2bfloat162_rn(pa[p].x, pa[p].y);
            d[1] = __floats2bfloat162_rn(pa[p].z, pa[p].w);
        }
    };
    auto loadB = [&](int k0) {
        if (BSRC_BF) {
            #pragma unroll
            for (int p = 0; p < 2; p++)
                pb16[p] = *(const uint4*)(Bb + (size_t)(k0 + br16 + p * 16) * N + bn + bc16);
        } else {
            #pragma unroll
            for (int p = 0; p < 4; p++)
                pb32[p] = *(const float4*)(Bf + (size_t)(k0 + br32 + p * 8) * N + bn + bc32);
        }
    };
    auto storeB = [&](int buf) {
        if (BSRC_BF) {
            #pragma unroll
            for (int p = 0; p < 2; p++)
                *(uint4*)&Bs[buf][(br16 + p * 16) * LDB + bc16] = pb16[p];
        } else {
            #pragma unroll
            for (int p = 0; p < 4; p++) {
                __nv_bfloat162* d = (__nv_bfloat162*)&Bs[buf][(br32 + p * 8) * LDB + bc32];
                d[0] = __floats2bfloat162_rn(pb32[p].x, pb32[p].y);
                d[1] = __floats2bfloat162_rn(pb32[p].z, pb32[p].w);
            }
        }
    };

    // ---- ldmatrix smem addresses ----
    const uint32_t a_base = (uint32_t)__cvta_generic_to_shared(&As[0][0]);
    const uint32_t b_base = (uint32_t)__cvta_generic_to_shared(&Bs[0][0]);
    const uint32_t a_off = ((wm + (lane & 15)) * LDA + ((lane >> 4) & 1) * 8) * 2;
    const uint32_t b_off = (((lane & 15)) * LDB + wn + ((lane >> 4) & 1) * 8) * 2;

    float acc[2][4][4] = {};

    loadA(0); loadB(0);
    storeA(0); storeB(0);
    __syncthreads();

    const int KT = K / BK;
    for (int kt = 0; kt < KT; kt++) {
        const int buf = kt & 1;
        if (kt + 1 < KT) { loadA((kt + 1) * BK); loadB((kt + 1) * BK); }

        #pragma unroll
        for (int ks = 0; ks < 2; ks++) {
            uint32_t af[2][4], bfr[2][4];
            #pragma unroll
            for (int mt = 0; mt < 2; mt++)
                ldsm_x4(af[mt], a_base + buf * ABYTES + a_off + (mt * 16 * LDA) * 2 + ks * 32);
            #pragma unroll
            for (int p = 0; p < 2; p++)
                ldsm_x4_t(bfr[p], b_base + buf * BBYTES + b_off + (p * 16) * 2 + ks * 16 * LDB * 2);
            #pragma unroll
            for (int mt = 0; mt < 2; mt++) {
                mma_bf16(acc[mt][0], af[mt], bfr[0][0], bfr[0][1]);
                mma_bf16(acc[mt][1], af[mt], bfr[0][2], bfr[0][3]);
                mma_bf16(acc[mt][2], af[mt], bfr[1][0], bfr[1][1]);
                mma_bf16(acc[mt][3], af[mt], bfr[1][2], bfr[1][3]);
            }
        }
        if (kt + 1 < KT) { storeA(buf ^ 1); storeB(buf ^ 1); }
        __syncthreads();
    }

    // ---- epilogue ----
    const int r0 = bm + wm + (lane >> 2);
    const int c0 = bn + wn + (lane & 3) * 2;
    #pragma unroll
    for (int mt = 0; mt < 2; mt++) {
        #pragma unroll
        for (int nt = 0; nt < 4; nt++) {
            const int r = r0 + mt * 16;
            const int cix = c0 + nt * 8;
            float b0 = BIAS ? bias[cix] : 0.f;
            float b1 = BIAS ? bias[cix + 1] : 0.f;
            float v0 = acc[mt][nt][0] + b0, v1 = acc[mt][nt][1] + b1;
            float v2 = acc[mt][nt][2] + b0, v3 = acc[mt][nt][3] + b1;
            if (OUT_BF) {
                __nv_bfloat16* C = (__nv_bfloat16*)Cv;
                *(__nv_bfloat162*)(C + (size_t)r * N + cix)       = __floats2bfloat162_rn(v0, v1);
                *(__nv_bfloat162*)(C + (size_t)(r + 8) * N + cix) = __floats2bfloat162_rn(v2, v3);
            } else {
                float* C = (float*)Cv;
                *(float2*)(C + (size_t)r * N + cix)       = make_float2(v0, v1);
                *(float2*)(C + (size_t)(r + 8) * N + cix) = make_float2(v2, v3);
            }
        }
    }
}

// ---------------- conversion / small kernels ---------------------------------
__global__ void f2bf_copy(const float* __restrict__ src, __nv_bfloat16* __restrict__ dst, size_t n4) {
    size_t i = (size_t)blockIdx.x * blockDim.x + threadIdx.x;
    size_t stride = (size_t)gridDim.x * blockDim.x;
    for (; i < n4; i += stride) {
        float4 v = ((const float4*)src)[i];
        __nv_bfloat162* d = (__nv_bfloat162*)(dst + i * 4);
        d[0] = __floats2bfloat162_rn(v.x, v.y);
        d[1] = __floats2bfloat162_rn(v.z, v.w);
    }
}

__global__ void f2bf_cat(const float* __restrict__ src, int Rows, int Cols,
                         __nv_bfloat16* __restrict__ dst, int dstLd, int rowOff, int colOff) {
    int idx = blockIdx.x * blockDim.x + threadIdx.x;
    int total = Rows * Cols;
    if (idx >= total) return;
    int r = idx / Cols, c = idx % Cols;
    dst[(size_t)(r + rowOff) * dstLd + colOff + c] = __float2bfloat16(src[idx]);
}

__global__ void build_bqb(const float* __restrict__ ba, const float* __restrict__ bbeta,
                          float* __restrict__ bqb) {
    int i = blockIdx.x * blockDim.x + threadIdx.x;
    if (i < 1536) bqb[i] = (i < 1024) ? ba[i] : bbeta[i - 1024];
}

__global__ void gather_emb(const int* __restrict__ cap, const float* __restrict__ emb,
                           float* __restrict__ capemb) {
    int idx = blockIdx.x * blockDim.x + threadIdx.x;
    int e  = idx % E;
    int bt = idx / E;
    int tok = cap[bt];
    capemb[idx] = emb[(size_t)tok * E + e];
}

__global__ void row_mean(const float* __restrict__ feats, float* __restrict__ mean) {
    int b = blockIdx.x;
    int e = threadIdx.x;
    float s = 0.f;
    const float* base = feats + (size_t)b * L * E + e;
    for (int l = 0; l < L; l++) s += base[(size_t)l * E];
    mean[b * E + e] = s * (1.0f / (float)L);
}

__global__ void copy_h_ctx(const float* __restrict__ h, float* __restrict__ ctx2) {
    int idx = blockIdx.x * blockDim.x + threadIdx.x;  // B*H
    int b = idx / H, j = idx % H;
    ctx2[(size_t)b * 2048 + 1024 + j] = h[idx];
}

// e[b,l] = relu(q[b,:] + keys[b,l,:]) . V_a + b_va ; 14 l's per block
__global__ __launch_bounds__(128) void attn_e(
    const __nv_bfloat16* __restrict__ keys, const float* __restrict__ qb,
    const float* __restrict__ Va, const float* __restrict__ bva, float* __restrict__ e)
{
    const int b = blockIdx.y;
    const int tid = threadIdx.x;
    __shared__ float qs[H];
    __shared__ float vs[H];
    __shared__ float red[4];
    for (int i = tid; i < H; i += 128) {
        qs[i] = qb[(size_t)b * 1536 + i];
        vs[i] = Va[i];
    }
    __syncthreads();

    const int i0 = tid * 8;
    for (int lg = 0; lg < 14; lg++) {
        const int l = blockIdx.x * 14 + lg;
        uint4 kv = *(const uint4*)(keys + ((size_t)b * L + l) * H + i0);
        const __nv_bfloat162* kp = (const __nv_bfloat162*)&kv;
        float s = 0.f;
        #pragma unroll
        for (int j = 0; j < 4; j++) {
            float2 kf = __bfloat1622float2(kp[j]);
            int i = i0 + j * 2;
            float v0 = fmaxf(qs[i] + kf.x, 0.f);
            float v1 = fmaxf(qs[i + 1] + kf.y, 0.f);
            s = fmaf(v0, vs[i], s);
            s = fmaf(v1, vs[i + 1], s);
        }
        s = warpReduceSum(s);
        if ((tid & 31) == 0) red[tid >> 5] = s;
        __syncthreads();
        if (tid == 0) e[b * L + l] = red[0] + red[1] + red[2] + red[3] + bva[0];
        __syncthreads();
    }
}

__global__ void softmax_L(const float* __restrict__ e, float* __restrict__ alpha) {
    int b = blockIdx.x;
    int tid = threadIdx.x;
    __shared__ float sm[256];
    float v = (tid < L) ? e[b * L + tid] : -1e30f;
    sm[tid] = v; __syncthreads();
    for (int s = 128; s > 0; s >>= 1) { if (tid < s) sm[tid] = fmaxf(sm[tid], sm[tid + s]); __syncthreads(); }
    float m = sm[0]; __syncthreads();
    float ex = (tid < L) ? __expf(v - m) : 0.f;
    sm[tid] = ex; __syncthreads();
    for (int s = 128; s > 0; s >>= 1) { if (tid < s) sm[tid] += sm[tid + s]; __syncthreads(); }
    float inv = 1.0f / sm[0];
    if (tid < L) alpha[b * L + tid] = ex * inv;
}

// z = sum_l alpha*feats ; ctx2[:,0:512] = z*sigmoid(gbuf) ; ctx2[:,512:1024] = x_t
__global__ __launch_bounds__(512) void z_ctx(
    const float* __restrict__ alpha, const float* __restrict__ feats,
    const float* __restrict__ qb, const float* __restrict__ capemb,
    int t, float* __restrict__ ctx2)
{
    const int b = blockIdx.x;
    const int e = threadIdx.x;   // 512
    __shared__ float al[L];
    for (int l = e; l < L; l += 512) al[l] = alpha[b * L + l];
    __syncthreads();
    float s = 0.f;
    const float* base = feats + (size_t)b * L * E + e;
    for (int l = 0; l < L; l++) s = fmaf(al[l], base[(size_t)l * E], s);
    float gb = qb[(size_t)b * 1536 + 1024 + e];
    ctx2[(size_t)b * 2048 + e]       = s * sigmoidf(gb);
    ctx2[(size_t)b * 2048 + 512 + e] = capemb[((size_t)b * T + t) * E + e];
}

__global__ void lstm_elem(const float* __restrict__ gates, float* __restrict__ h,
                          float* __restrict__ c, float* __restrict__ ctx2) {
    int idx = blockIdx.x * blockDim.x + threadIdx.x;  // B*H
    int b = idx / H, j = idx % H;
    const float* g = gates + (size_t)b * 4 * H;
    float i_ = sigmoidf(g[j]);
    float f_ = sigmoidf(g[H + j]);
    float gg = tanhf(g[2 * H + j]);
    float o_ = sigmoidf(g[3 * H + j]);
    float cn = f_ * c[idx] + i_ * gg;
    c[idx] = cn;
    float hn = o_ * tanhf(cn);
    h[idx] = hn;
    ctx2[(size_t)b * 2048 + 1024 + j] = hn;
}

__global__ void softmax_V(const float* __restrict__ logits, float* __restrict__ out, int t) {
    int b = blockIdx.x;
    int tid = threadIdx.x;  // 256
    const float* x = logits + (size_t)b * V;
    float* y = out + ((size_t)b * T + t) * V;
    __shared__ float sm[8];

    float m = -1e30f;
    for (int i = tid; i < V; i += 256) m = fmaxf(m, x[i]);
    #pragma unroll
    for (int o = 16; o > 0; o >>= 1) m = fmaxf(m, __shfl_xor_sync(0xFFFFFFFFu, m, o));
    if ((tid & 31) == 0) sm[tid >> 5] = m;
    __syncthreads();
    float mm = fmaxf(fmaxf(fmaxf(sm[0], sm[1]), fmaxf(sm[2], sm[3])),
                     fmaxf(fmaxf(sm[4], sm[5]), fmaxf(sm[6], sm[7])));
    __syncthreads();

    float s = 0.f;
    for (int i = tid; i < V; i += 256) s += __expf(x[i] - mm);
    s = warpReduceSum(s);
    if ((tid & 31) == 0) sm[tid >> 5] = s;
    __syncthreads();
    float ss = sm[0] + sm[1] + sm[2] + sm[3] + sm[4] + sm[5] + sm[6] + sm[7];
    float inv = 1.0f / ss;
    for (int i = tid; i < V; i += 256) y[i] = __expf(x[i] - mm) * inv;
}

// ---------------- launch ------------------------------------------------------
extern "C" void kernel_launch(void* const* d_in, const int* in_sizes, int n_in,
                              void* d_out, int out_size) {
    const int*   cap      = (const int*)  d_in[0];
    const float* feats    = (const float*)d_in[1];
    const float* emb      = (const float*)d_in[2];
    const float* W_init_h = (const float*)d_in[3];
    const float* b_init_h = (const float*)d_in[4];
    const float* W_init_c = (const float*)d_in[5];
    const float* b_init_c = (const float*)d_in[6];
    const float* W_a      = (const float*)d_in[7];
    const float* b_a      = (const float*)d_in[8];
    const float* U_a      = (const float*)d_in[9];
    const float* b_ua     = (const float*)d_in[10];
    const float* V_a      = (const float*)d_in[11];
    const float* b_va     = (const float*)d_in[12];
    const float* W_beta   = (const float*)d_in[13];
    const float* b_beta   = (const float*)d_in[14];
    const float* W_lstm   = (const float*)d_in[15];
    const float* U_lstm   = (const float*)d_in[16];
    const float* b_lstm   = (const float*)d_in[17];
    const float* W_out    = (const float*)d_in[18];
    const float* b_out    = (const float*)d_in[19];
    float* out = (float*)d_out;

    __nv_bfloat16 *keys, *wout, *wg, *wqb;
    float *bqb, *h, *c, *qb, *eb, *alpha, *ctx2, *gates, *logits, *capemb, *meanv;
    cudaGetSymbolAddress((void**)&keys,   g_keys_bf);
    cudaGetSymbolAddress((void**)&wout,   g_wout_bf);
    cudaGetSymbolAddress((void**)&wg,     g_wg_bf);
    cudaGetSymbolAddress((void**)&wqb,    g_wqb_bf);
    cudaGetSymbolAddress((void**)&bqb,    g_bqb);
    cudaGetSymbolAddress((void**)&h,      g_h);
    cudaGetSymbolAddress((void**)&c,      g_c);
    cudaGetSymbolAddress((void**)&qb,     g_qb);
    cudaGetSymbolAddress((void**)&eb,     g_e);
    cudaGetSymbolAddress((void**)&alpha,  g_alpha);
    cudaGetSymbolAddress((void**)&ctx2,   g_ctx2);
    cudaGetSymbolAddress((void**)&gates,  g_gates);
    cudaGetSymbolAddress((void**)&logits, g_logits);
    cudaGetSymbolAddress((void**)&capemb, g_capemb);
    cudaGetSymbolAddress((void**)&meanv,  g_mean);

    // ---- prologue: conversions & concatenations ----
    f2bf_copy<<<2048, 256>>>(W_out, wout, (size_t)H * V / 4);
    f2bf_cat<<<(1024 * 1024) / 256, 256>>>(W_a,    1024, 1024, wqb, 1536, 0, 0);
    f2bf_cat<<<(1024 * 512)  / 256, 256>>>(W_beta, 1024, 512,  wqb, 1536, 0, 1024);
    f2bf_cat<<<(1024 * 4096) / 256, 256>>>(W_lstm, 1024, 4096, wg,  4096, 0, 0);
    f2bf_cat<<<(1024 * 4096) / 256, 256>>>(U_lstm, 1024, 4096, wg,  4096, 1024, 0);
    build_bqb<<<6, 256>>>(b_a, b_beta, bqb);

    gather_emb<<<(B * T * E) / 256, 256>>>(cap, emb, capemb);
    row_mean<<<B, E>>>(feats, meanv);

    // init h0 / c0
    gemm_tc<false, false, true><<<dim3(H / BN, B / BM), 128>>>(meanv, W_init_h, b_init_h, h, B, H, E);
    gemm_tc<false, false, true><<<dim3(H / BN, B / BM), 128>>>(meanv, W_init_c, b_init_c, c, B, H, E);
    copy_h_ctx<<<(B * H) / 256, 256>>>(h, ctx2);

    // keys = (feats @ U_a + b_ua) -> bf16
    gemm_tc<false, true, true><<<dim3(H / BN, (B * L) / BM), 128>>>(feats, U_a, b_ua, keys, B * L, H, E);

    // ---- time steps ----
    for (int t = 0; t < T; t++) {
        // [q | gbuf] = h @ [W_a | W_beta] + [b_a | b_beta]
        gemm_tc<true, false, true><<<dim3(1536 / BN, B / BM), 128>>>(h, wqb, bqb, qb, B, 1536, H);
        attn_e<<<dim3(14, B), 128>>>(keys, qb, V_a, b_va, eb);
        softmax_L<<<B, 256>>>(eb, alpha);
        z_ctx<<<B, 512>>>(alpha, feats, qb, capemb, t, ctx2);
        // gates = [zbeta, x_t, h] @ [W_lstm ; U_lstm] + b_lstm
        gemm_tc<true, false, true><<<dim3(4096 / BN, B / BM), 128>>>(ctx2, wg, b_lstm, gates, B, 4096, 2048);
        lstm_elem<<<(B * H) / 256, 256>>>(gates, h, c, ctx2);
        // logits = h @ W_out + b_out ; out[:, t, :] = softmax(logits)
        gemm_tc<true, false, true><<<dim3(V / BN, B / BM), 128>>>(h, wout, b_out, logits, B, V, H);
        softmax_V<<<B, 256>>>(logits, out, t);
    }
}

// round 4
// speedup vs baseline: 5.8989x; 1.5731x over previous
#include <cuda_runtime.h>
#include <cuda_bf16.h>
#include <cstdint>

// Problem constants
constexpr int B = 128, T = 16, L = 196, E = 512, H = 1024, V = 32000;

// ---------------- scratch (device globals; no allocations allowed) ----------
__device__ __nv_bfloat16 g_keys[(size_t)B * L * H];        // 51.4 MB
__device__ __nv_bfloat16 g_featsbf[(size_t)B * L * E];     // 25.7 MB
__device__ __nv_bfloat16 g_woutbf[(size_t)H * V];          // 65.5 MB [K,N]
__device__ __nv_bfloat16 g_wgbf[(size_t)2048 * 4096];      // 16.8 MB [K,N]
__device__ __nv_bfloat16 g_wqbbf[(size_t)1024 * 1536];     // 3.1 MB  [K,N]
__device__ __nv_bfloat16 g_wihbf[(size_t)E * H];
__device__ __nv_bfloat16 g_wicbf[(size_t)E * H];
__device__ __nv_bfloat16 g_uabf[(size_t)E * H];
__device__ __nv_bfloat16 g_hbf[B * H];
__device__ __nv_bfloat16 g_ctx2[B * 2048];
__device__ __nv_bfloat16 g_meanbf[B * E];
__device__ __nv_bfloat16 g_capemb[(size_t)B * T * E];
__device__ float g_c[B * H];
__device__ float g_qb[B * 1536];
__device__ float g_qbp[4 * B * 1536];
__device__ float g_bqb[1536];
__device__ float g_e[B * L];
__device__ float g_alpha[B * L];
__device__ float g_gatesp[4 * B * 4096];
__device__ float g_logits[(size_t)B * V];                  // 16.4 MB

// ---------------- helpers ---------------------------------------------------
__device__ __forceinline__ float warpReduceSum(float v) {
    #pragma unroll
    for (int o = 16; o > 0; o >>= 1) v += __shfl_xor_sync(0xFFFFFFFFu, v, o);
    return v;
}
__device__ __forceinline__ float warpReduceMax(float v) {
    #pragma unroll
    for (int o = 16; o > 0; o >>= 1) v = fmaxf(v, __shfl_xor_sync(0xFFFFFFFFu, v, o));
    return v;
}
__device__ __forceinline__ float sigmoidf(float x) { return 1.0f / (1.0f + __expf(-x)); }

__device__ __forceinline__ void ldsm_x4(uint32_t* r, uint32_t addr) {
    asm volatile("ldmatrix.sync.aligned.m8n8.x4.shared.b16 {%0,%1,%2,%3}, [%4];"
                 : "=r"(r[0]), "=r"(r[1]), "=r"(r[2]), "=r"(r[3]) : "r"(addr));
}
__device__ __forceinline__ void ldsm_x4_t(uint32_t* r, uint32_t addr) {
    asm volatile("ldmatrix.sync.aligned.m8n8.x4.trans.shared.b16 {%0,%1,%2,%3}, [%4];"
                 : "=r"(r[0]), "=r"(r[1]), "=r"(r[2]), "=r"(r[3]) : "r"(addr));
}
__device__ __forceinline__ void mma_bf16(float* c, const uint32_t* a, uint32_t b0, uint32_t b1) {
    asm volatile(
        "mma.sync.aligned.m16n8k16.row.col.f32.bf16.bf16.f32 "
        "{%0,%1,%2,%3},{%4,%5,%6,%7},{%8,%9},{%0,%1,%2,%3};"
        : "+f"(c[0]), "+f"(c[1]), "+f"(c[2]), "+f"(c[3])
        : "r"(a[0]), "r"(a[1]), "r"(a[2]), "r"(a[3]), "r"(b0), "r"(b1));
}
__device__ __forceinline__ void cp16(uint32_t dst, const void* src) {
    asm volatile("cp.async.cg.shared.global [%0], [%1], 16;" :: "r"(dst), "l"(src) : "memory");
}
#define CP_COMMIT() asm volatile("cp.async.commit_group;" ::: "memory")
#define CP_WAIT(n)  asm volatile("cp.async.wait_group %0;" :: "n"(n) : "memory")

// ---------------- HMMA GEMM: C = A[MxK](bf16) @ Bw[KxN](bf16) (+bias) -------
// BM=128, BN=128, BK=32, 256 threads (8 warps as 2M x 4N of 64x32 warp tiles),
// 3-stage cp.async pipeline. Requires M%128==0, N%128==0, (K/SPLITK)%32==0.
// SPLITK>1: each z-block writes its partial to C + z*M*N (f32, no bias).
constexpr int ASTG = 128 * 80;           // A stage bytes (LDA=40 bf16)
constexpr int BSTG = 32 * 272;           // B stage bytes (LDB=136 bf16)
constexpr int STG  = ASTG + BSTG;        // 18944
constexpr int GSMEM = 3 * STG;           // 56832

template <int SPLITK, bool OUT_BF, bool BIAS>
__global__ __launch_bounds__(256) void gemm_hmma(
    const __nv_bfloat16* __restrict__ A, const __nv_bfloat16* __restrict__ Bw,
    const float* __restrict__ bias, void* __restrict__ Cv, int M, int N, int K)
{
    extern __shared__ char sm[];
    const int tid  = threadIdx.x;
    const int lane = tid & 31;
    const int warp = tid >> 5;
    const int wm = (warp & 1) * 64;
    const int wn = (warp >> 1) * 32;
    const int m0 = blockIdx.y * 128;
    const int n0 = blockIdx.x * 128;
    const int Kc = K / SPLITK;
    const int kbase = (SPLITK > 1) ? blockIdx.z * Kc : 0;
    const int KT = Kc / 32;

    const uint32_t smb = (uint32_t)__cvta_generic_to_shared(sm);

    auto issue = [&](int kt, int s) {
        const int k0 = kbase + kt * 32;
        const uint32_t base = smb + s * STG;
        // A: 128 rows x 32 cols bf16 = 512 x 16B chunks
        {
            int i = tid;                    // chunk 0
            int row = i >> 2, cc = i & 3;
            cp16(base + row * 80 + cc * 16, A + (size_t)(m0 + row) * K + k0 + cc * 8);
            i = tid + 256;
            row = i >> 2; cc = i & 3;
            cp16(base + row * 80 + cc * 16, A + (size_t)(m0 + row) * K + k0 + cc * 8);
        }
        // B: 32 rows x 128 cols bf16 = 512 x 16B chunks
        {
            int i = tid;
            int row = i >> 4, cc = i & 15;
            cp16(base + ASTG + row * 272 + cc * 16, Bw + (size_t)(k0 + row) * N + n0 + cc * 8);
            i = tid + 256;
            row = i >> 4; cc = i & 15;
            cp16(base + ASTG + row * 272 + cc * 16, Bw + (size_t)(k0 + row) * N + n0 + cc * 8);
        }
    };

    float acc[4][4][4] = {};

    issue(0, 0); CP_COMMIT();
    if (KT > 1) { issue(1, 1); CP_COMMIT(); }

    for (int kt = 0; kt < KT; kt++) {
        CP_WAIT(1);
        __syncthreads();
        if (kt + 2 < KT) issue(kt + 2, (kt + 2) % 3);
        CP_COMMIT();

        const uint32_t ab = smb + (kt % 3) * STG;
        const uint32_t bb = ab + ASTG;
        #pragma unroll
        for (int ks = 0; ks < 2; ks++) {
            uint32_t a[4][4], b0[4], b1[4];
            #pragma unroll
            for (int mt = 0; mt < 4; mt++)
                ldsm_x4(a[mt], ab + (wm + mt * 16 + (lane & 15)) * 80
                                  + ks * 32 + ((lane >> 4) & 1) * 16);
            const uint32_t brow = bb + (ks * 16 + (lane & 15)) * 272
                                     + (wn + ((lane >> 4) & 1) * 8) * 2;
            ldsm_x4_t(b0, brow);
            ldsm_x4_t(b1, brow + 32);
            #pragma unroll
            for (int mt = 0; mt < 4; mt++) {
                mma_bf16(acc[mt][0], a[mt], b0[0], b0[1]);
                mma_bf16(acc[mt][1], a[mt], b0[2], b0[3]);
                mma_bf16(acc[mt][2], a[mt], b1[0], b1[1]);
                mma_bf16(acc[mt][3], a[mt], b1[2], b1[3]);
            }
        }
        __syncthreads();
    }

    // ---- epilogue ----
    const int r0 = m0 + wm + (lane >> 2);
    const int c0 = n0 + wn + (lane & 3) * 2;
    #pragma unroll
    for (int mt = 0; mt < 4; mt++) {
        #pragma unroll
        for (int nt = 0; nt < 4; nt++) {
            const int r = r0 + mt * 16;
            const int cix = c0 + nt * 8;
            float b0v = BIAS ? bias[cix] : 0.f;
            float b1v = BIAS ? bias[cix + 1] : 0.f;
            float v0 = acc[mt][nt][0] + b0v, v1 = acc[mt][nt][1] + b1v;
            float v2 = acc[mt][nt][2] + b0v, v3 = acc[mt][nt][3] + b1v;
            if (OUT_BF) {
                __nv_bfloat16* C = (__nv_bfloat16*)Cv;
                *(__nv_bfloat162*)(C + (size_t)r * N + cix)       = __floats2bfloat162_rn(v0, v1);
                *(__nv_bfloat162*)(C + (size_t)(r + 8) * N + cix) = __floats2bfloat162_rn(v2, v3);
            } else {
                float* C = (float*)Cv + (SPLITK > 1 ? (size_t)blockIdx.z * M * N : 0);
                *(float2*)(C + (size_t)r * N + cix)       = make_float2(v0, v1);
                *(float2*)(C + (size_t)(r + 8) * N + cix) = make_float2(v2, v3);
            }
        }
    }
}

// ---------------- prologue kernels -------------------------------------------
__global__ void f2bf_copy(const float* __restrict__ src, __nv_bfloat16* __restrict__ dst, size_t n4) {
    size_t i = (size_t)blockIdx.x * blockDim.x + threadIdx.x;
    size_t stride = (size_t)gridDim.x * blockDim.x;
    for (; i < n4; i += stride) {
        float4 v = ((const float4*)src)[i];
        __nv_bfloat162* d = (__nv_bfloat162*)(dst + i * 4);
        d[0] = __floats2bfloat162_rn(v.x, v.y);
        d[1] = __floats2bfloat162_rn(v.z, v.w);
    }
}

__global__ void f2bf_cat(const float* __restrict__ src, int Rows, int Cols,
                         __nv_bfloat16* __restrict__ dst, int dstLd, int rowOff, int colOff) {
    int idx = blockIdx.x * blockDim.x + threadIdx.x;
    if (idx >= Rows * Cols) return;
    int r = idx / Cols, c = idx % Cols;
    dst[(size_t)(r + rowOff) * dstLd + colOff + c] = __float2bfloat16(src[idx]);
}

__global__ void build_bqb(const float* __restrict__ ba, const float* __restrict__ bbeta,
                          float* __restrict__ bqb) {
    int i = blockIdx.x * blockDim.x + threadIdx.x;
    if (i < 1536) bqb[i] = (i < 1024) ? ba[i] : bbeta[i - 1024];
}

__global__ void gather_emb(const int* __restrict__ cap, const float* __restrict__ emb,
                           __nv_bfloat16* __restrict__ capemb) {
    int idx = blockIdx.x * blockDim.x + threadIdx.x;   // B*T*E
    int e = idx % E, bt = idx / E;
    capemb[idx] = __float2bfloat16(emb[(size_t)cap[bt] * E + e]);
}

__global__ void row_mean(const float* __restrict__ feats, __nv_bfloat16* __restrict__ mean) {
    int b = blockIdx.x, e = threadIdx.x;               // blockDim = 512
    float s = 0.f;
    const float* base = feats + (size_t)b * L * E + e;
    for (int l = 0; l < L; l++) s += base[(size_t)l * E];
    mean[b * E + e] = __float2bfloat16(s * (1.0f / (float)L));
}

__global__ void copy_h0(const __nv_bfloat16* __restrict__ hbf, __nv_bfloat16* __restrict__ ctx2) {
    int idx = blockIdx.x * blockDim.x + threadIdx.x;   // B*H
    int b = idx / H, j = idx % H;
    ctx2[(size_t)b * 2048 + 1024 + j] = hbf[idx];
}

// ---------------- per-step small kernels -------------------------------------
__global__ void qb_reduce(const float* __restrict__ qbp, const float* __restrict__ bqb,
                          float* __restrict__ qb) {
    int idx = blockIdx.x * blockDim.x + threadIdx.x;   // B*1536
    int col = idx % 1536;
    float s = bqb[col];
    #pragma unroll
    for (int z = 0; z < 4; z++) s += qbp[(size_t)z * B * 1536 + idx];
    qb[idx] = s;
}

__global__ __launch_bounds__(128) void attn_e(
    const __nv_bfloat16* __restrict__ keys, const float* __restrict__ qb,
    const float* __restrict__ Va, const float* __restrict__ bva, float* __restrict__ e)
{
    const int b = blockIdx.y;
    const int tid = threadIdx.x;
    __shared__ float qs[H];
    __shared__ float vs[H];
    __shared__ float red[4];
    for (int i = tid; i < H; i += 128) {
        qs[i] = qb[(size_t)b * 1536 + i];
        vs[i] = Va[i];
    }
    __syncthreads();

    const int i0 = tid * 8;
    for (int lg = 0; lg < 14; lg++) {
        const int l = blockIdx.x * 14 + lg;
        uint4 kv = *(const uint4*)(keys + ((size_t)b * L + l) * H + i0);
        const __nv_bfloat162* kp = (const __nv_bfloat162*)&kv;
        float s = 0.f;
        #pragma unroll
        for (int j = 0; j < 4; j++) {
            float2 kf = __bfloat1622float2(kp[j]);
            int i = i0 + j * 2;
            s = fmaf(fmaxf(qs[i] + kf.x, 0.f), vs[i], s);
            s = fmaf(fmaxf(qs[i + 1] + kf.y, 0.f), vs[i + 1], s);
        }
        s = warpReduceSum(s);
        if ((tid & 31) == 0) red[tid >> 5] = s;
        __syncthreads();
        if (tid == 0) e[b * L + l] = red[0] + red[1] + red[2] + red[3] + bva[0];
        __syncthreads();
    }
}

__global__ void softmax_L(const float* __restrict__ e, float* __restrict__ alpha) {
    int b = blockIdx.x, tid = threadIdx.x;            // 256
    __shared__ float sm[256];
    float v = (tid < L) ? e[b * L + tid] : -1e30f;
    sm[tid] = v; __syncthreads();
    for (int s = 128; s > 0; s >>= 1) { if (tid < s) sm[tid] = fmaxf(sm[tid], sm[tid + s]); __syncthreads(); }
    float m = sm[0]; __syncthreads();
    float ex = (tid < L) ? __expf(v - m) : 0.f;
    sm[tid] = ex; __syncthreads();
    for (int s = 128; s > 0; s >>= 1) { if (tid < s) sm[tid] += sm[tid + s]; __syncthreads(); }
    float inv = 1.0f / sm[0];
    if (tid < L) alpha[b * L + tid] = ex * inv;
}

// z = sum_l alpha*feats (4-way L split); ctx2[0:512]=bf(z*sig(gbuf)); ctx2[512:1024]=x_t
__global__ __launch_bounds__(512) void z_ctx(
    const float* __restrict__ alpha, const float* __restrict__ feats,
    const float* __restrict__ qb, const __nv_bfloat16* __restrict__ capemb,
    int t, __nv_bfloat16* __restrict__ ctx2)
{
    const int b = blockIdx.x, tid = threadIdx.x;
    const int grp = tid >> 7, col = tid & 127;        // 4 groups x 128 float4-cols
    __shared__ float al[L];
    __shared__ float4 part[4][128];
    for (int i = tid; i < L; i += 512) al[i] = alpha[b * L + i];
    __syncthreads();
    const float4* base = (const float4*)(feats + (size_t)b * L * E) + col;
    float4 s = make_float4(0.f, 0.f, 0.f, 0.f);
    const int l0 = grp * 49;
    #pragma unroll 4
    for (int l = l0; l < l0 + 49; l++) {
        float a = al[l];
        float4 f = base[(size_t)l * 128];
        s.x = fmaf(a, f.x, s.x); s.y = fmaf(a, f.y, s.y);
        s.z = fmaf(a, f.z, s.z); s.w = fmaf(a, f.w, s.w);
    }
    part[grp][col] = s;
    __syncthreads();
    if (grp == 0) {
        float4 a0 = part[0][col], a1 = part[1][col], a2 = part[2][col], a3 = part[3][col];
        float zx = a0.x + a1.x + a2.x + a3.x;
        float zy = a0.y + a1.y + a2.y + a3.y;
        float zz = a0.z + a1.z + a2.z + a3.z;
        float zw = a0.w + a1.w + a2.w + a3.w;
        const float* gb = qb + (size_t)b * 1536 + 1024 + col * 4;
        __nv_bfloat16* d = ctx2 + (size_t)b * 2048 + col * 4;
        d[0] = __float2bfloat16(zx * sigmoidf(gb[0]));
        d[1] = __float2bfloat16(zy * sigmoidf(gb[1]));
        d[2] = __float2bfloat16(zz * sigmoidf(gb[2]));
        d[3] = __float2bfloat16(zw * sigmoidf(gb[3]));
    } else if (grp == 1) {
        const uint64_t* src = (const uint64_t*)(capemb + ((size_t)b * T + t) * E);
        uint64_t* dst = (uint64_t*)(ctx2 + (size_t)b * 2048 + 512);
        dst[col] = src[col];
    }
}

__global__ void lstm_elem(const float* __restrict__ gp, const float* __restrict__ blstm,
                          float* __restrict__ c, __nv_bfloat16* __restrict__ hbf,
                          __nv_bfloat16* __restrict__ ctx2) {
    int idx = blockIdx.x * blockDim.x + threadIdx.x;  // B*H
    int b = idx / H, j = idx % H;
    const size_t base = (size_t)b * 4096;
    float gi = blstm[j], gf = blstm[H + j], gg = blstm[2 * H + j], go = blstm[3 * H + j];
    #pragma unroll
    for (int z = 0; z < 4; z++) {
        const float* g = gp + (size_t)z * B * 4096 + base;
        gi += g[j]; gf += g[H + j]; gg += g[2 * H + j]; go += g[3 * H + j];
    }
    float i_ = sigmoidf(gi), f_ = sigmoidf(gf), g_ = tanhf(gg), o_ = sigmoidf(go);
    float cn = f_ * c[idx] + i_ * g_;
    c[idx] = cn;
    __nv_bfloat16 hn = __float2bfloat16(o_ * tanhf(cn));
    hbf[idx] = hn;
    ctx2[(size_t)b * 2048 + 1024 + j] = hn;
}

__global__ __launch_bounds__(1024) void softmax_V(const float* __restrict__ logits,
                                                  float* __restrict__ out, int t) {
    extern __shared__ float xs[];                      // 32000 floats
    const int b = blockIdx.x, tid = threadIdx.x;
    const float* x = logits + (size_t)b * V;
    float* y = out + ((size_t)b * T + t) * V;
    __shared__ float red[32];

    float m = -1e30f;
    for (int i = tid; i < V; i += 1024) { float v = x[i]; xs[i] = v; m = fmaxf(m, v); }
    m = warpReduceMax(m);
    if ((tid & 31) == 0) red[tid >> 5] = m;
    __syncthreads();
    if (tid < 32) { float v = red[tid]; v = warpReduceMax(v); red[tid] = v; }
    __syncthreads();
    const float mm = red[0];

    float s = 0.f;
    for (int i = tid; i < V; i += 1024) s += __expf(xs[i] - mm);
    s = warpReduceSum(s);
    __syncthreads();
    if ((tid & 31) == 0) red[tid >> 5] = s;
    __syncthreads();
    if (tid < 32) { float v = red[tid]; v = warpReduceSum(v); red[tid] = v; }
    __syncthreads();
    const float inv = 1.0f / red[0];
    for (int i = tid; i < V; i += 1024) y[i] = __expf(xs[i] - mm) * inv;
}

// ---------------- launch ------------------------------------------------------
extern "C" void kernel_launch(void* const* d_in, const int* in_sizes, int n_in,
                              void* d_out, int out_size) {
    const int*   cap      = (const int*)  d_in[0];
    const float* feats    = (const float*)d_in[1];
    const float* emb      = (const float*)d_in[2];
    const float* W_init_h = (const float*)d_in[3];
    const float* b_init_h = (const float*)d_in[4];
    const float* W_init_c = (const float*)d_in[5];
    const float* b_init_c = (const float*)d_in[6];
    const float* W_a      = (const float*)d_in[7];
    const float* b_a      = (const float*)d_in[8];
    const float* U_a      = (const float*)d_in[9];
    const float* b_ua     = (const float*)d_in[10];
    const float* V_a      = (const float*)d_in[11];
    const float* b_va     = (const float*)d_in[12];
    const float* W_beta   = (const float*)d_in[13];
    const float* b_beta   = (const float*)d_in[14];
    const float* W_lstm   = (const float*)d_in[15];
    const float* U_lstm   = (const float*)d_in[16];
    const float* b_lstm   = (const float*)d_in[17];
    const float* W_out    = (const float*)d_in[18];
    const float* b_out    = (const float*)d_in[19];
    float* out = (float*)d_out;

    __nv_bfloat16 *keys, *featsbf, *woutbf, *wgbf, *wqbbf, *wihbf, *wicbf, *uabf,
                  *hbf, *ctx2, *meanbf, *capemb;
    float *cst, *qb, *qbp, *bqb, *eb, *alpha, *gatesp, *logits;
    cudaGetSymbolAddress((void**)&keys,    g_keys);
    cudaGetSymbolAddress((void**)&featsbf, g_featsbf);
    cudaGetSymbolAddress((void**)&woutbf,  g_woutbf);
    cudaGetSymbolAddress((void**)&wgbf,    g_wgbf);
    cudaGetSymbolAddress((void**)&wqbbf,   g_wqbbf);
    cudaGetSymbolAddress((void**)&wihbf,   g_wihbf);
    cudaGetSymbolAddress((void**)&wicbf,   g_wicbf);
    cudaGetSymbolAddress((void**)&uabf,    g_uabf);
    cudaGetSymbolAddress((void**)&hbf,     g_hbf);
    cudaGetSymbolAddress((void**)&ctx2,    g_ctx2);
    cudaGetSymbolAddress((void**)&meanbf,  g_meanbf);
    cudaGetSymbolAddress((void**)&capemb,  g_capemb);
    cudaGetSymbolAddress((void**)&cst,     g_c);
    cudaGetSymbolAddress((void**)&qb,      g_qb);
    cudaGetSymbolAddress((void**)&qbp,     g_qbp);
    cudaGetSymbolAddress((void**)&bqb,     g_bqb);
    cudaGetSymbolAddress((void**)&eb,      g_e);
    cudaGetSymbolAddress((void**)&alpha,   g_alpha);
    cudaGetSymbolAddress((void**)&gatesp,  g_gatesp);
    cudaGetSymbolAddress((void**)&logits,  g_logits);

    cudaFuncSetAttribute(gemm_hmma<1, true,  true>,  cudaFuncAttributeMaxDynamicSharedMemorySize, GSMEM);
    cudaFuncSetAttribute(gemm_hmma<1, false, true>,  cudaFuncAttributeMaxDynamicSharedMemorySize, GSMEM);
    cudaFuncSetAttribute(gemm_hmma<4, false, false>, cudaFuncAttributeMaxDynamicSharedMemorySize, GSMEM);
    cudaFuncSetAttribute(softmax_V, cudaFuncAttributeMaxDynamicSharedMemorySize, V * 4);

    // ---- prologue: bf16 weight copies ([K,N] layout kept) ----
    f2bf_copy<<<2048, 256>>>(W_out, woutbf, (size_t)H * V / 4);
    f2bf_copy<<<512, 256>>>(W_init_h, wihbf, (size_t)E * H / 4);
    f2bf_copy<<<512, 256>>>(W_init_c, wicbf, (size_t)E * H / 4);
    f2bf_copy<<<512, 256>>>(U_a, uabf, (size_t)E * H / 4);
    f2bf_cat<<<(1024 * 1024) / 256, 256>>>(W_a,    1024, 1024, wqbbf, 1536, 0, 0);
    f2bf_cat<<<(1024 * 512)  / 256, 256>>>(W_beta, 1024, 512,  wqbbf, 1536, 0, 1024);
    f2bf_cat<<<(1024 * 4096) / 256, 256>>>(W_lstm, 1024, 4096, wgbf,  4096, 0, 0);
    f2bf_cat<<<(1024 * 4096) / 256, 256>>>(U_lstm, 1024, 4096, wgbf,  4096, 1024, 0);
    build_bqb<<<6, 256>>>(b_a, b_beta, bqb);

    f2bf_copy<<<2048, 256>>>(feats, featsbf, (size_t)B * L * E / 4);
    gather_emb<<<(B * T * E) / 256, 256>>>(cap, emb, capemb);
    row_mean<<<B, 512>>>(feats, meanbf);

    // h0 / c0
    gemm_hmma<1, true,  true><<<dim3(8, 1), 256, GSMEM>>>(meanbf, wihbf, b_init_h, hbf, 128, H, E);
    gemm_hmma<1, false, true><<<dim3(8, 1), 256, GSMEM>>>(meanbf, wicbf, b_init_c, cst, 128, H, E);
    copy_h0<<<(B * H) / 256, 256>>>(hbf, ctx2);

    // keys = feats @ U_a + b_ua -> bf16 [B*L, H]
    gemm_hmma<1, true, true><<<dim3(8, B * L / 128), 256, GSMEM>>>(featsbf, uabf, b_ua, keys, B * L, H, E);

    // ---- time steps ----
    for (int t = 0; t < T; t++) {
        gemm_hmma<4, false, false><<<dim3(12, 1, 4), 256, GSMEM>>>(hbf, wqbbf, nullptr, qbp, 128, 1536, 1024);
        qb_reduce<<<(B * 1536) / 256, 256>>>(qbp, bqb, qb);
        attn_e<<<dim3(14, B), 128>>>(keys, qb, V_a, b_va, eb);
        softmax_L<<<B, 256>>>(eb, alpha);
        z_ctx<<<B, 512>>>(alpha, feats, qb, capemb, t, ctx2);
        gemm_hmma<4, false, false><<<dim3(32, 1, 4), 256, GSMEM>>>(ctx2, wgbf, nullptr, gatesp, 128, 4096, 2048);
        lstm_elem<<<(B * H) / 256, 256>>>(gatesp, b_lstm, cst, hbf, ctx2);
        gemm_hmma<1, false, true><<<dim3(V / 128, 1), 256, GSMEM>>>(hbf, woutbf, b_out, logits, 128, V, H);
        softmax_V<<<B, 1024, V * 4>>>(logits, out, t);
    }
}